// round 16
// baseline (speedup 1.0000x reference)
#include <cuda_runtime.h>
#include <cuda_bf16.h>
#include <cstdint>

// MotionLoss: per-row small-angle HTM chain + global MSE reduction.
// inputs  : [512,1024,18] f32   (d_in[0])  -> TMA 4-stage smem pipeline
// targets : [512,1024, 7] f32   (d_in[1])  -> direct register LDG (no smem),
//                                             issued before the TMA wait
// out     : scalar f32
//
// Targets ride the LDG path OUTSIDE smem: tile shrinks to 9.2KB -> 6 CTAs/SM
// (6 TMA streams), inputs in-flight 221KB/SM + targets bytes in LDG flight.
// First config whose total outstanding bytes exceed the smem capacity cap
// that every previous variant was re-partitioning.

#define TPB 128
#define ROWS_TILE 128
#define NSTAGE 4
#define NBLK 888                       // 6 CTAs/SM * 148 SMs

#define TILE_IN_FLOATS (ROWS_TILE * 18)        // 2304
#define TILE_IN_BYTES  (TILE_IN_FLOATS * 4)    // 9216

__device__ float g_partials[NBLK];
__device__ unsigned int g_ticket = 0;

__device__ __forceinline__ uint32_t smem_u32(const void* p) {
    return (uint32_t)__cvta_generic_to_shared(p);
}
__device__ __forceinline__ void mbar_init(uint32_t addr, uint32_t count) {
    asm volatile("mbarrier.init.shared.b64 [%0], %1;" :: "r"(addr), "r"(count) : "memory");
}
__device__ __forceinline__ void mbar_expect_tx(uint32_t addr, uint32_t bytes) {
    asm volatile("mbarrier.arrive.expect_tx.shared.b64 _, [%0], %1;"
                 :: "r"(addr), "r"(bytes) : "memory");
}
__device__ __forceinline__ uint64_t make_evict_last_policy() {
    uint64_t pol;
    asm volatile("createpolicy.fractional.L2::evict_last.b64 %0, 1.0;" : "=l"(pol));
    return pol;
}
__device__ __forceinline__ void bulk_g2s_hint(uint32_t dst, const void* src,
                                              uint32_t bytes, uint32_t mbar,
                                              uint64_t pol) {
    asm volatile(
        "cp.async.bulk.shared::cluster.global.mbarrier::complete_tx::bytes.L2::cache_hint "
        "[%0], [%1], %2, [%3], %4;"
        :: "r"(dst), "l"(src), "r"(bytes), "r"(mbar), "l"(pol) : "memory");
}
__device__ __forceinline__ float ldg_hint(const float* p, uint64_t pol) {
    float v;
    asm volatile("ld.global.nc.L2::cache_hint.f32 %0, [%1], %2;"
                 : "=f"(v) : "l"(p), "l"(pol));
    return v;
}
__device__ __forceinline__ void mbar_wait(uint32_t addr, uint32_t parity) {
    uint32_t done;
    asm volatile(
        "{\n\t.reg .pred p;\n\t"
        "mbarrier.try_wait.parity.acquire.cta.shared::cta.b64 p, [%1], %2;\n\t"
        "selp.b32 %0, 1, 0, p;\n\t}"
        : "=r"(done) : "r"(addr), "r"(parity) : "memory");
    if (!done) {
        asm volatile(
            "{\n\t.reg .pred P1;\n\t"
            "WAIT_LOOP_%=:\n\t"
            "mbarrier.try_wait.parity.acquire.cta.shared::cta.b64 P1, [%0], %1, 0x989680;\n\t"
            "@P1 bra.uni WAIT_DONE_%=;\n\t"
            "bra.uni WAIT_LOOP_%=;\n\t"
            "WAIT_DONE_%=:\n\t}"
            :: "r"(addr), "r"(parity) : "memory");
    }
}

__global__ __launch_bounds__(TPB) void motion_loss_split(
    const float* __restrict__ in, const float* __restrict__ tgt,
    float* __restrict__ out, int n_rows)
{
    extern __shared__ float smem[];                 // [NSTAGE*TILE_IN_FLOATS] + barriers
    uint64_t* mbar = (uint64_t*)(smem + NSTAGE * TILE_IN_FLOATS);

    const int T = n_rows / ROWS_TILE;               // 4096 full tiles
    const int bid = blockIdx.x;
    const int tid = threadIdx.x;

    if (tid == 0) {
        #pragma unroll
        for (int s = 0; s < NSTAGE; ++s) mbar_init(smem_u32(&mbar[s]), 1);
    }
    asm volatile("fence.proxy.async.shared::cta;" ::: "memory");
    __syncthreads();

    const uint64_t pol = make_evict_last_policy();

    auto issue_tile = [&](int tile, int slot) {     // tid==0 only
        uint32_t bar = smem_u32(&mbar[slot]);
        uint32_t dst = smem_u32(smem + slot * TILE_IN_FLOATS);
        mbar_expect_tx(bar, TILE_IN_BYTES);
        bulk_g2s_hint(dst, in + (size_t)tile * TILE_IN_FLOATS,
                      TILE_IN_BYTES, bar, pol);
    };

    // ---- prologue: fill NSTAGE-1 stages ----
    if (tid == 0) {
        for (int it = 0; it < NSTAGE - 1; ++it) {
            int tile = bid + it * NBLK;
            if (tile < T) issue_tile(tile, it);
        }
    }

    // ---- main loop (bottom-issue) ----
    float acc = 0.0f;
    int it = 0;
    for (int tile = bid; tile < T; tile += NBLK, ++it) {
        // Targets: direct register loads, issued BEFORE the TMA wait so their
        // L2 latency overlaps the wait. 28B row stride -> all sectors consumed,
        // L1 absorbs the per-line reuse across the 7 loads.
        const float* tp = tgt + ((size_t)tile * ROWS_TILE + tid) * 7;
        const float t0 = ldg_hint(tp + 0, pol);
        const float t1 = ldg_hint(tp + 1, pol);
        const float t2 = ldg_hint(tp + 2, pol);
        const float t3 = ldg_hint(tp + 3, pol);
        const float x  = ldg_hint(tp + 4, pol);
        const float y  = ldg_hint(tp + 5, pol);
        const float z  = ldg_hint(tp + 6, pol);

        const int slot = it % NSTAGE;
        const uint32_t parity = (uint32_t)((it / NSTAGE) & 1);
        mbar_wait(smem_u32(&mbar[slot]), parity);

        const float* vp = &smem[slot * TILE_IN_FLOATS + tid * 18];

        // float2 reads: 9 LDS.64 (72B row stride, 8B aligned)
        const float2* v2 = (const float2*)vp;
        float2 q0 = v2[0], q1 = v2[1], q2 = v2[2], q3 = v2[3], q4 = v2[4];
        float2 q5 = v2[5], q6 = v2[6], q7 = v2[7], q8 = v2[8];
        const float p0 = q0.x, p1 = q0.y, p2 = q1.x;
        const float s00 = q1.y, s01 = q2.x;
        const float s10 = q2.y, s11 = q3.x;
        const float s20 = q3.y, s21 = q4.x;
        const float exX = q4.y, eyX = q5.x, ezX = q5.y;
        const float exY = q6.x, eyY = q6.y, ezY = q7.x;
        const float exZ = q7.y, eyZ = q8.x, ezZ = q8.y;

        // w = MX * (MY * (MZ * P)), P=(x,y,z,1)
        float ax = x - ezZ * y + eyZ * z + s20;
        float ay = ezZ * x + y - exZ * z + s21;
        float az = -eyZ * x + exZ * y + z + p2;
        float bx = ax - ezY * ay + eyY * az + s10;
        float by = ezY * ax + ay - exY * az + p1;
        float bz = -eyY * ax + exY * ay + az + s11;
        float cx = bx - ezX * by + eyX * bz + p0;
        float cy = ezX * bx + by - exX * bz + s00;
        float cz = -eyX * bx + exX * by + bz + s01;

        const float m1 = cx - x;
        const float m2 = cy - y;
        const float m3 = cz - z;
        const float err = sqrtf(m1 * m1 + m2 * m2 + m3 * m3 + 1e-12f);

        const float d0 = err - t0;
        const float d1 = m1 - t1;
        const float d2 = m2 - t2;
        const float d3 = m3 - t3;
        acc += d0 * d0 + d1 * d1 + d2 * d2 + d3 * d3;

        __syncthreads();            // all readers done before slot reuse

        if (tid == 0) {
            int nxt_it = it + NSTAGE - 1;
            int nxt_tile = bid + nxt_it * NBLK;
            if (nxt_tile < T) issue_tile(nxt_tile, nxt_it % NSTAGE);
        }
    }

    // ---- block reduction (deterministic) ----
    #pragma unroll
    for (int off = 16; off > 0; off >>= 1)
        acc += __shfl_down_sync(0xFFFFFFFFu, acc, off);

    __shared__ float s_warp[TPB / 32];
    const int lane = tid & 31;
    const int wid  = tid >> 5;
    if (lane == 0) s_warp[wid] = acc;
    __syncthreads();
    if (wid == 0) {
        float a = (lane < TPB / 32) ? s_warp[lane] : 0.0f;   // 4 warps
        #pragma unroll
        for (int off = 2; off > 0; off >>= 1)
            a += __shfl_down_sync(0xFFFFFFFFu, a, off);
        if (lane == 0) g_partials[bid] = a;
    }

    // ---- last-block-done final reduce ----
    __shared__ bool s_last;
    __threadfence();
    if (tid == 0) {
        unsigned int tk = atomicAdd(&g_ticket, 1u);
        s_last = (tk == gridDim.x - 1);
    }
    __syncthreads();
    if (!s_last) return;

    double sum = 0.0;
    for (int i = tid; i < (int)gridDim.x; i += TPB)
        sum += (double)__ldcg(&g_partials[i]);

    if (tid == 0) {   // remainder rows (none for 512*1024; safety)
        for (int r = T * ROWS_TILE; r < n_rows; ++r) {
            const float* v = in + (size_t)r * 18;
            const float* t = tgt + (size_t)r * 7;
            float x = t[4], y = t[5], z = t[6];
            float ax = x - v[17]*y + v[16]*z + v[7];
            float ay = v[17]*x + y - v[15]*z + v[8];
            float az = -v[16]*x + v[15]*y + z + v[2];
            float bx = ax - v[14]*ay + v[13]*az + v[5];
            float by = v[14]*ax + ay - v[12]*az + v[1];
            float bz = -v[13]*ax + v[12]*ay + az + v[6];
            float cx = bx - v[11]*by + v[10]*bz + v[0];
            float cy = v[11]*bx + by - v[9]*bz + v[3];
            float cz = -v[10]*bx + v[9]*by + bz + v[4];
            float m1 = cx - x, m2 = cy - y, m3 = cz - z;
            float err = sqrtf(m1*m1 + m2*m2 + m3*m3 + 1e-12f);
            float d0 = err - t[0], d1 = m1 - t[1], d2 = m2 - t[2], d3 = m3 - t[3];
            sum += (double)(d0*d0 + d1*d1 + d2*d2 + d3*d3);
        }
    }

    __shared__ double s_fin[TPB];
    s_fin[tid] = sum;
    __syncthreads();
    #pragma unroll
    for (int off = TPB / 2; off > 0; off >>= 1) {
        if (tid < off) s_fin[tid] += s_fin[tid + off];
        __syncthreads();
    }
    if (tid == 0) {
        out[0] = (float)(s_fin[0] / ((double)n_rows * 4.0));
        g_ticket = 0;   // reset for next graph replay
    }
}

extern "C" void kernel_launch(void* const* d_in, const int* in_sizes, int n_in,
                              void* d_out, int out_size)
{
    const float* inputs  = (const float*)d_in[0];
    const float* targets = (const float*)d_in[1];
    float* out = (float*)d_out;

    const int n_rows = in_sizes[0] / 18;                        // 524288
    const int smem_bytes = NSTAGE * TILE_IN_BYTES + NSTAGE * 8; // 36896

    static bool attr_set = false;
    if (!attr_set) {
        cudaFuncSetAttribute(motion_loss_split,
                             cudaFuncAttributeMaxDynamicSharedMemorySize,
                             smem_bytes);
        attr_set = true;
    }

    motion_loss_split<<<NBLK, TPB, smem_bytes>>>(inputs, targets, out, n_rows);
}

// round 17
// speedup vs baseline: 1.0067x; 1.0067x over previous
#include <cuda_runtime.h>
#include <cuda_bf16.h>
#include <cstdint>

// MotionLoss: per-row small-angle HTM chain + global MSE reduction.
// inputs  : [512,1024,18] f32   (d_in[0])  -> TMA 4-stage smem pipeline
// targets : [512,1024, 7] f32   (d_in[1])  -> register-double-buffered LDG,
//                                             prefetched ONE FULL TILE ahead
// out     : scalar f32
//
// R16 retry with the exposed-latency bug fixed: target LDGs for tile it+1 are
// issued at the top of iteration it, consumed one tile-period later. 6 CTAs/SM
// (9.2KB tiles), 6 TMA streams/SM, targets ride outside the smem cap.

#define TPB 128
#define ROWS_TILE 128
#define NSTAGE 4
#define NBLK 888                       // 6 CTAs/SM * 148 SMs

#define TILE_IN_FLOATS (ROWS_TILE * 18)        // 2304
#define TILE_IN_BYTES  (TILE_IN_FLOATS * 4)    // 9216

__device__ float g_partials[NBLK];
__device__ unsigned int g_ticket = 0;

__device__ __forceinline__ uint32_t smem_u32(const void* p) {
    return (uint32_t)__cvta_generic_to_shared(p);
}
__device__ __forceinline__ void mbar_init(uint32_t addr, uint32_t count) {
    asm volatile("mbarrier.init.shared.b64 [%0], %1;" :: "r"(addr), "r"(count) : "memory");
}
__device__ __forceinline__ void mbar_expect_tx(uint32_t addr, uint32_t bytes) {
    asm volatile("mbarrier.arrive.expect_tx.shared.b64 _, [%0], %1;"
                 :: "r"(addr), "r"(bytes) : "memory");
}
__device__ __forceinline__ uint64_t make_evict_last_policy() {
    uint64_t pol;
    asm volatile("createpolicy.fractional.L2::evict_last.b64 %0, 1.0;" : "=l"(pol));
    return pol;
}
__device__ __forceinline__ void bulk_g2s_hint(uint32_t dst, const void* src,
                                              uint32_t bytes, uint32_t mbar,
                                              uint64_t pol) {
    asm volatile(
        "cp.async.bulk.shared::cluster.global.mbarrier::complete_tx::bytes.L2::cache_hint "
        "[%0], [%1], %2, [%3], %4;"
        :: "r"(dst), "l"(src), "r"(bytes), "r"(mbar), "l"(pol) : "memory");
}
__device__ __forceinline__ float ldg_hint(const float* p, uint64_t pol) {
    float v;
    asm volatile("ld.global.nc.L2::cache_hint.f32 %0, [%1], %2;"
                 : "=f"(v) : "l"(p), "l"(pol));
    return v;
}
__device__ __forceinline__ void mbar_wait(uint32_t addr, uint32_t parity) {
    uint32_t done;
    asm volatile(
        "{\n\t.reg .pred p;\n\t"
        "mbarrier.try_wait.parity.acquire.cta.shared::cta.b64 p, [%1], %2;\n\t"
        "selp.b32 %0, 1, 0, p;\n\t}"
        : "=r"(done) : "r"(addr), "r"(parity) : "memory");
    if (!done) {
        asm volatile(
            "{\n\t.reg .pred P1;\n\t"
            "WAIT_LOOP_%=:\n\t"
            "mbarrier.try_wait.parity.acquire.cta.shared::cta.b64 P1, [%0], %1, 0x989680;\n\t"
            "@P1 bra.uni WAIT_DONE_%=;\n\t"
            "bra.uni WAIT_LOOP_%=;\n\t"
            "WAIT_DONE_%=:\n\t}"
            :: "r"(addr), "r"(parity) : "memory");
    }
}

__global__ __launch_bounds__(TPB) void motion_loss_split2(
    const float* __restrict__ in, const float* __restrict__ tgt,
    float* __restrict__ out, int n_rows)
{
    extern __shared__ float smem[];                 // [NSTAGE*TILE_IN_FLOATS] + barriers
    uint64_t* mbar = (uint64_t*)(smem + NSTAGE * TILE_IN_FLOATS);

    const int T = n_rows / ROWS_TILE;               // 4096 full tiles
    const int bid = blockIdx.x;
    const int tid = threadIdx.x;

    if (tid == 0) {
        #pragma unroll
        for (int s = 0; s < NSTAGE; ++s) mbar_init(smem_u32(&mbar[s]), 1);
    }
    asm volatile("fence.proxy.async.shared::cta;" ::: "memory");
    __syncthreads();

    const uint64_t pol = make_evict_last_policy();

    auto issue_tile = [&](int tile, int slot) {     // tid==0 only
        uint32_t bar = smem_u32(&mbar[slot]);
        uint32_t dst = smem_u32(smem + slot * TILE_IN_FLOATS);
        mbar_expect_tx(bar, TILE_IN_BYTES);
        bulk_g2s_hint(dst, in + (size_t)tile * TILE_IN_FLOATS,
                      TILE_IN_BYTES, bar, pol);
    };

    // ---- prologue: fill NSTAGE-1 input stages; load first tile's targets ----
    if (tid == 0) {
        for (int it = 0; it < NSTAGE - 1; ++it) {
            int tile = bid + it * NBLK;
            if (tile < T) issue_tile(tile, it);
        }
    }

    float c0 = 0.f, c1 = 0.f, c2 = 0.f, c3 = 0.f, cx0 = 0.f, cy0 = 0.f, cz0 = 0.f;
    {
        const float* tp = tgt + ((size_t)bid * ROWS_TILE + tid) * 7;
        c0 = ldg_hint(tp + 0, pol);  c1 = ldg_hint(tp + 1, pol);
        c2 = ldg_hint(tp + 2, pol);  c3 = ldg_hint(tp + 3, pol);
        cx0 = ldg_hint(tp + 4, pol); cy0 = ldg_hint(tp + 5, pol);
        cz0 = ldg_hint(tp + 6, pol);
    }

    // ---- main loop (bottom-issue TMA, targets prefetched one tile ahead) ----
    float acc = 0.0f;
    int it = 0;
    for (int tile = bid; tile < T; tile += NBLK, ++it) {
        // Prefetch NEXT tile's targets into 'n*' regs; consumed next iteration
        // (one full tile-period of latency hiding).
        float n0 = 0.f, n1 = 0.f, n2 = 0.f, n3 = 0.f, nx = 0.f, ny = 0.f, nz = 0.f;
        const int ntile = tile + NBLK;
        if (ntile < T) {
            const float* tp = tgt + ((size_t)ntile * ROWS_TILE + tid) * 7;
            n0 = ldg_hint(tp + 0, pol);  n1 = ldg_hint(tp + 1, pol);
            n2 = ldg_hint(tp + 2, pol);  n3 = ldg_hint(tp + 3, pol);
            nx = ldg_hint(tp + 4, pol);  ny = ldg_hint(tp + 5, pol);
            nz = ldg_hint(tp + 6, pol);
        }

        const int slot = it % NSTAGE;
        const uint32_t parity = (uint32_t)((it / NSTAGE) & 1);
        mbar_wait(smem_u32(&mbar[slot]), parity);

        const float* vp = &smem[slot * TILE_IN_FLOATS + tid * 18];

        // float2 reads: 9 LDS.64 (72B row stride, 8B aligned)
        const float2* v2 = (const float2*)vp;
        float2 q0 = v2[0], q1 = v2[1], q2 = v2[2], q3 = v2[3], q4 = v2[4];
        float2 q5 = v2[5], q6 = v2[6], q7 = v2[7], q8 = v2[8];
        const float p0 = q0.x, p1 = q0.y, p2 = q1.x;
        const float s00 = q1.y, s01 = q2.x;
        const float s10 = q2.y, s11 = q3.x;
        const float s20 = q3.y, s21 = q4.x;
        const float exX = q4.y, eyX = q5.x, ezX = q5.y;
        const float exY = q6.x, eyY = q6.y, ezY = q7.x;
        const float exZ = q7.y, eyZ = q8.x, ezZ = q8.y;

        const float x = cx0, y = cy0, z = cz0;

        // w = MX * (MY * (MZ * P)), P=(x,y,z,1)
        float ax = x - ezZ * y + eyZ * z + s20;
        float ay = ezZ * x + y - exZ * z + s21;
        float az = -eyZ * x + exZ * y + z + p2;
        float bx = ax - ezY * ay + eyY * az + s10;
        float by = ezY * ax + ay - exY * az + p1;
        float bz = -eyY * ax + exY * ay + az + s11;
        float cxx = bx - ezX * by + eyX * bz + p0;
        float cyy = ezX * bx + by - exX * bz + s00;
        float czz = -eyX * bx + exX * by + bz + s01;

        const float m1 = cxx - x;
        const float m2 = cyy - y;
        const float m3 = czz - z;
        const float err = sqrtf(m1 * m1 + m2 * m2 + m3 * m3 + 1e-12f);

        const float d0 = err - c0;
        const float d1 = m1 - c1;
        const float d2 = m2 - c2;
        const float d3 = m3 - c3;
        acc += d0 * d0 + d1 * d1 + d2 * d2 + d3 * d3;

        // rotate target buffers
        c0 = n0; c1 = n1; c2 = n2; c3 = n3; cx0 = nx; cy0 = ny; cz0 = nz;

        __syncthreads();            // all readers done before slot reuse

        if (tid == 0) {
            int nxt_it = it + NSTAGE - 1;
            int nxt_tile = bid + nxt_it * NBLK;
            if (nxt_tile < T) issue_tile(nxt_tile, nxt_it % NSTAGE);
        }
    }

    // ---- block reduction (deterministic) ----
    #pragma unroll
    for (int off = 16; off > 0; off >>= 1)
        acc += __shfl_down_sync(0xFFFFFFFFu, acc, off);

    __shared__ float s_warp[TPB / 32];
    const int lane = tid & 31;
    const int wid  = tid >> 5;
    if (lane == 0) s_warp[wid] = acc;
    __syncthreads();
    if (wid == 0) {
        float a = (lane < TPB / 32) ? s_warp[lane] : 0.0f;   // 4 warps
        #pragma unroll
        for (int off = 2; off > 0; off >>= 1)
            a += __shfl_down_sync(0xFFFFFFFFu, a, off);
        if (lane == 0) g_partials[bid] = a;
    }

    // ---- last-block-done final reduce ----
    __shared__ bool s_last;
    __threadfence();
    if (tid == 0) {
        unsigned int tk = atomicAdd(&g_ticket, 1u);
        s_last = (tk == gridDim.x - 1);
    }
    __syncthreads();
    if (!s_last) return;

    double sum = 0.0;
    for (int i = tid; i < (int)gridDim.x; i += TPB)
        sum += (double)__ldcg(&g_partials[i]);

    if (tid == 0) {   // remainder rows (none for 512*1024; safety)
        for (int r = T * ROWS_TILE; r < n_rows; ++r) {
            const float* v = in + (size_t)r * 18;
            const float* t = tgt + (size_t)r * 7;
            float x = t[4], y = t[5], z = t[6];
            float ax = x - v[17]*y + v[16]*z + v[7];
            float ay = v[17]*x + y - v[15]*z + v[8];
            float az = -v[16]*x + v[15]*y + z + v[2];
            float bx = ax - v[14]*ay + v[13]*az + v[5];
            float by = v[14]*ax + ay - v[12]*az + v[1];
            float bz = -v[13]*ax + v[12]*ay + az + v[6];
            float cx = bx - v[11]*by + v[10]*bz + v[0];
            float cy = v[11]*bx + by - v[9]*bz + v[3];
            float cz = -v[10]*bx + v[9]*by + bz + v[4];
            float m1 = cx - x, m2 = cy - y, m3 = cz - z;
            float err = sqrtf(m1*m1 + m2*m2 + m3*m3 + 1e-12f);
            float d0 = err - t[0], d1 = m1 - t[1], d2 = m2 - t[2], d3 = m3 - t[3];
            sum += (double)(d0*d0 + d1*d1 + d2*d2 + d3*d3);
        }
    }

    __shared__ double s_fin[TPB];
    s_fin[tid] = sum;
    __syncthreads();
    #pragma unroll
    for (int off = TPB / 2; off > 0; off >>= 1) {
        if (tid < off) s_fin[tid] += s_fin[tid + off];
        __syncthreads();
    }
    if (tid == 0) {
        out[0] = (float)(s_fin[0] / ((double)n_rows * 4.0));
        g_ticket = 0;   // reset for next graph replay
    }
}

extern "C" void kernel_launch(void* const* d_in, const int* in_sizes, int n_in,
                              void* d_out, int out_size)
{
    const float* inputs  = (const float*)d_in[0];
    const float* targets = (const float*)d_in[1];
    float* out = (float*)d_out;

    const int n_rows = in_sizes[0] / 18;                        // 524288
    const int smem_bytes = NSTAGE * TILE_IN_BYTES + NSTAGE * 8; // 36896

    static bool attr_set = false;
    if (!attr_set) {
        cudaFuncSetAttribute(motion_loss_split2,
                             cudaFuncAttributeMaxDynamicSharedMemorySize,
                             smem_bytes);
        attr_set = true;
    }

    motion_loss_split2<<<NBLK, TPB, smem_bytes>>>(inputs, targets, out, n_rows);
}